// round 3
// baseline (speedup 1.0000x reference)
#include <cuda_runtime.h>
#include <cstdint>
#include <math.h>

#define NTOK 16384
#define SEQ_MASK 4095
#define DM 1024
#define BM 128
#define BN 256
#define BK 16
#define AST 20     // A smem row stride (floats): conflict-free a-frag LDS
#define BST 264    // B smem row stride (floats): 264 % 32 == 8 -> conflict-free b-frag LDS
#define ASTAGE (BM * AST)   // 2560 floats
#define BSTAGE (BK * BST)   // 4224 floats
#define NSTAGE 3
#define SMEM_FLOATS (NSTAGE * (ASTAGE + BSTAGE))  // 20352 floats = 81408 B

// Scratch (allocation-free rule: __device__ globals)
__device__ float g_Q[(size_t)NTOK * DM];
__device__ float g_K[(size_t)NTOK * DM];
__device__ float g_V[(size_t)NTOK * DM];
__device__ float g_X[(size_t)NTOK * DM];      // tf32-rounded x
__device__ float g_W[3][(size_t)DM * DM];     // tf32-rounded Wq, Wk, Wv
__device__ float g_cos[4096 * 32];
__device__ float g_sin[4096 * 32];

__device__ __forceinline__ uint32_t to_tf32(float x) {
    uint32_t u;
    asm("cvt.rna.tf32.f32 %0, %1;" : "=r"(u) : "f"(x));
    return u;
}

// Round fp32 -> tf32 (rna), store as fp32 (tf32 values are exact fp32)
__global__ void cvt_tf32_kernel(const float4* __restrict__ src, float4* __restrict__ dst, int n4) {
    int i = blockIdx.x * blockDim.x + threadIdx.x;
    if (i >= n4) return;
    float4 v = src[i];
    float4 o;
    o.x = __uint_as_float(to_tf32(v.x));
    o.y = __uint_as_float(to_tf32(v.y));
    o.z = __uint_as_float(to_tf32(v.z));
    o.w = __uint_as_float(to_tf32(v.w));
    dst[i] = o;
}

// RoPE cos/sin table: 32 fp64 exps total, fast sincos on range-reduced angle.
__global__ void rope_table_kernel() {
    int k = blockIdx.x;  // 0..31
    double freq = exp((double)(-2 * k) * (log(10000.0) / 1024.0));
    const double TWO_PI = 6.283185307179586476925287;
    for (int s = threadIdx.x; s < 4096; s += blockDim.x) {
        double ang = (double)s * freq;
        double n = floor(ang * (1.0 / TWO_PI) + 0.5);
        float r = (float)(ang - n * TWO_PI);
        float ss, cc;
        __sincosf(r, &ss, &cc);
        g_cos[s * 32 + k] = cc;
        g_sin[s * 32 + k] = ss;
    }
}

__device__ __forceinline__ void cp16(uint32_t smem_addr, const float* gptr) {
    asm volatile("cp.async.ca.shared.global [%0], [%1], 16;\n" ::"r"(smem_addr), "l"(gptr));
}

// C[M,N] = X[M,K] @ W[K,N] + bias (+ optional RoPE on output pairs)
// X, W already tf32-rounded. 256 threads, block tile 128x256, warp tile 64x64,
// 3-stage cp.async pipeline.
__global__ __launch_bounds__(256, 1)
void gemm_kernel(const float* __restrict__ X, const float* __restrict__ W,
                 const float* __restrict__ bias, float* __restrict__ out,
                 int do_rope) {
    extern __shared__ float sm[];
    int tid = threadIdx.x;
    int lane = tid & 31;
    int warp = tid >> 5;
    int g = lane >> 2;      // group (row within fragment)
    int t = lane & 3;
    int wm = (warp >> 2) * 64;  // warp grid 2(M) x 4(N)
    int wn = (warp & 3) * 64;
    int bm = blockIdx.y * BM;
    int bn = blockIdx.x * BN;

    float acc[4][8][4];
#pragma unroll
    for (int i = 0; i < 4; i++)
#pragma unroll
        for (int j = 0; j < 8; j++)
#pragma unroll
            for (int c = 0; c < 4; c++) acc[i][j][c] = 0.f;

    uint32_t sbase = (uint32_t)__cvta_generic_to_shared(sm);

    // A: 128 rows x 4 chunks of 16B -> 512 chunks, 2/thread
    // B: 16 rows x 64 chunks of 16B -> 1024 chunks, 4/thread
    auto issue_stage = [&](int kt) {
        int s = kt % NSTAGE;
        int k0 = kt * BK;
        uint32_t abase = sbase + (uint32_t)(s * ASTAGE) * 4u;
        uint32_t bbase = sbase + (uint32_t)(NSTAGE * ASTAGE + s * BSTAGE) * 4u;
#pragma unroll
        for (int u = 0; u < 2; u++) {
            int c = tid + u * 256;
            int r = c >> 2, kq = c & 3;
            cp16(abase + (uint32_t)(r * AST + kq * 4) * 4u,
                 X + (size_t)(bm + r) * DM + k0 + kq * 4);
        }
#pragma unroll
        for (int u = 0; u < 4; u++) {
            int c = tid + u * 256;
            int r = c >> 6, nq = c & 63;
            cp16(bbase + (uint32_t)(r * BST + nq * 4) * 4u,
                 W + (size_t)(k0 + r) * DM + bn + nq * 4);
        }
    };

    issue_stage(0);
    asm volatile("cp.async.commit_group;\n" ::);
    issue_stage(1);
    asm volatile("cp.async.commit_group;\n" ::);

    const int NKT = DM / BK;  // 64
    for (int kt = 0; kt < NKT; kt++) {
        asm volatile("cp.async.wait_group 1;\n" ::);
        __syncthreads();
        if (kt + 2 < NKT) issue_stage(kt + 2);
        asm volatile("cp.async.commit_group;\n" ::);

        int s = kt % NSTAGE;
        const float* As = sm + s * ASTAGE;
        const float* Bs = sm + NSTAGE * ASTAGE + s * BSTAGE;

#pragma unroll
        for (int ks = 0; ks < 2; ks++) {
            int kb = ks * 8;
            uint32_t a[4][4], b[8][2];
#pragma unroll
            for (int mi = 0; mi < 4; mi++) {
                int row = wm + mi * 16 + g;
                const float* ap = As + row * AST + kb + t;
                a[mi][0] = __float_as_uint(ap[0]);
                a[mi][1] = __float_as_uint(ap[8 * AST]);
                a[mi][2] = __float_as_uint(ap[4]);
                a[mi][3] = __float_as_uint(ap[8 * AST + 4]);
            }
#pragma unroll
            for (int ni = 0; ni < 8; ni++) {
                int col = wn + ni * 8 + g;
                const float* bp = Bs + (kb + t) * BST + col;
                b[ni][0] = __float_as_uint(bp[0]);
                b[ni][1] = __float_as_uint(bp[4 * BST]);
            }
#pragma unroll
            for (int mi = 0; mi < 4; mi++)
#pragma unroll
                for (int ni = 0; ni < 8; ni++)
                    asm volatile(
                        "mma.sync.aligned.m16n8k8.row.col.f32.tf32.tf32.f32 "
                        "{%0,%1,%2,%3}, {%4,%5,%6,%7}, {%8,%9}, {%0,%1,%2,%3};"
                        : "+f"(acc[mi][ni][0]), "+f"(acc[mi][ni][1]),
                          "+f"(acc[mi][ni][2]), "+f"(acc[mi][ni][3])
                        : "r"(a[mi][0]), "r"(a[mi][1]), "r"(a[mi][2]), "r"(a[mi][3]),
                          "r"(b[ni][0]), "r"(b[ni][1]));
        }
        __syncthreads();
    }

    // Epilogue: bias add (+ RoPE rotation on (even,odd) column pairs), write fp32
#pragma unroll
    for (int mi = 0; mi < 4; mi++) {
        int r0 = bm + wm + mi * 16 + g;
#pragma unroll
        for (int ni = 0; ni < 8; ni++) {
            int col = bn + wn + ni * 8 + 2 * t;  // even
            float b0 = bias[col], b1 = bias[col + 1];
#pragma unroll
            for (int h = 0; h < 2; h++) {
                int r = r0 + h * 8;
                float xe = acc[mi][ni][2 * h] + b0;
                float xo = acc[mi][ni][2 * h + 1] + b1;
                float2 v;
                if (do_rope) {
                    int kp = (col & 63) >> 1;
                    int ss = r & SEQ_MASK;
                    float c = g_cos[ss * 32 + kp];
                    float sn = g_sin[ss * 32 + kp];
                    v.x = xe * c - xo * sn;
                    v.y = xe * sn + xo * c;
                } else {
                    v.x = xe;
                    v.y = xo;
                }
                *(float2*)(out + (size_t)r * DM + col) = v;
            }
        }
    }
}

// Per-token attention over heads (Q/K already roped by GEMM epilogue).
__global__ __launch_bounds__(128)
void attn_kernel(float* __restrict__ out) {
    __shared__ __align__(16) float q[16][68];
    __shared__ __align__(16) float kk[16][68];
    __shared__ __align__(16) float v[16][68];
    __shared__ float sc[16][16];

    int tok = blockIdx.x;
    int tid = threadIdx.x;
    size_t base = (size_t)tok * DM;
    const float4* Q4 = (const float4*)(g_Q + base);
    const float4* K4 = (const float4*)(g_K + base);
    const float4* V4 = (const float4*)(g_V + base);

#pragma unroll
    for (int u = 0; u < 2; u++) {
        int c = tid + u * 128;
        int r = c >> 4, cc = c & 15;
        *(float4*)&q[r][cc * 4] = Q4[c];
        *(float4*)&kk[r][cc * 4] = K4[c];
        *(float4*)&v[r][cc * 4] = V4[c];
    }
    __syncthreads();

#pragma unroll
    for (int u = 0; u < 2; u++) {
        int p = tid + u * 128;
        int i = p >> 4, j = p & 15;
        const float4* qi = (const float4*)&q[i][0];
        const float4* kj = (const float4*)&kk[j][0];
        float a = 0.f;
#pragma unroll
        for (int d = 0; d < 16; d++) {
            float4 a4 = qi[d], b4 = kj[d];
            a += a4.x * b4.x + a4.y * b4.y + a4.z * b4.z + a4.w * b4.w;
        }
        sc[i][j] = a * 0.125f;  // 1/sqrt(64)
    }
    __syncthreads();

    if (tid < 16) {
        float m = sc[tid][0];
#pragma unroll
        for (int j = 1; j < 16; j++) m = fmaxf(m, sc[tid][j]);
        float sum = 0.f;
#pragma unroll
        for (int j = 0; j < 16; j++) {
            float e = __expf(sc[tid][j] - m);
            sc[tid][j] = e;
            sum += e;
        }
        float inv = 1.f / sum;
#pragma unroll
        for (int j = 0; j < 16; j++) sc[tid][j] *= inv;
    }
    __syncthreads();

    int i = tid >> 3, d0 = (tid & 7) * 8;
    float4 o0 = {0, 0, 0, 0}, o1 = {0, 0, 0, 0};
#pragma unroll
    for (int j = 0; j < 16; j++) {
        float a = sc[i][j];
        float4 v0 = *(const float4*)&v[j][d0];
        float4 v1 = *(const float4*)&v[j][d0 + 4];
        o0.x += a * v0.x; o0.y += a * v0.y; o0.z += a * v0.z; o0.w += a * v0.w;
        o1.x += a * v1.x; o1.y += a * v1.y; o1.z += a * v1.z; o1.w += a * v1.w;
    }
    *(float4*)(out + base + i * 64 + d0) = o0;
    *(float4*)(out + base + i * 64 + d0 + 4) = o1;
}

extern "C" void kernel_launch(void* const* d_in, const int* in_sizes, int n_in,
                              void* d_out, int out_size) {
    const float* x  = (const float*)d_in[0];
    const float* Wq = (const float*)d_in[1];
    const float* bq = (const float*)d_in[2];
    const float* Wk = (const float*)d_in[3];
    const float* bk = (const float*)d_in[4];
    const float* Wv = (const float*)d_in[5];
    const float* bv = (const float*)d_in[6];
    float* out = (float*)d_out;

    float *qp, *kp, *vp, *xp, *wp;
    cudaGetSymbolAddress((void**)&qp, g_Q);
    cudaGetSymbolAddress((void**)&kp, g_K);
    cudaGetSymbolAddress((void**)&vp, g_V);
    cudaGetSymbolAddress((void**)&xp, g_X);
    cudaGetSymbolAddress((void**)&wp, g_W);

    static int smem_set = 0;
    if (!smem_set) {
        cudaFuncSetAttribute(gemm_kernel, cudaFuncAttributeMaxDynamicSharedMemorySize,
                             SMEM_FLOATS * 4);
        smem_set = 1;
    }

    rope_table_kernel<<<32, 128>>>();

    int n4x = NTOK * DM / 4;
    cvt_tf32_kernel<<<n4x / 256, 256>>>((const float4*)x, (float4*)xp, n4x);
    int n4w = DM * DM / 4;
    cvt_tf32_kernel<<<n4w / 256, 256>>>((const float4*)Wq, (float4*)(wp + 0 * (size_t)DM * DM), n4w);
    cvt_tf32_kernel<<<n4w / 256, 256>>>((const float4*)Wk, (float4*)(wp + 1 * (size_t)DM * DM), n4w);
    cvt_tf32_kernel<<<n4w / 256, 256>>>((const float4*)Wv, (float4*)(wp + 2 * (size_t)DM * DM), n4w);

    dim3 grid(DM / BN, NTOK / BM);  // (4, 128)
    gemm_kernel<<<grid, 256, SMEM_FLOATS * 4>>>(xp, wp + 0 * (size_t)DM * DM, bq, qp, 1);
    gemm_kernel<<<grid, 256, SMEM_FLOATS * 4>>>(xp, wp + 1 * (size_t)DM * DM, bk, kp, 1);
    gemm_kernel<<<grid, 256, SMEM_FLOATS * 4>>>(xp, wp + 2 * (size_t)DM * DM, bv, vp, 0);

    attn_kernel<<<NTOK, 128>>>(out);
}

// round 8
// speedup vs baseline: 1.1619x; 1.1619x over previous
#include <cuda_runtime.h>
#include <cstdint>
#include <math.h>

#define NTOK 16384
#define SEQ_MASK 4095
#define DM 1024
#define BM 128
#define BN 128
#define BK 16
#define AST 20     // A smem row stride (floats): 20g mod 32 = {0,4,..,28} -> conflict-free
#define BST 136    // B smem row stride (floats): 136 mod 32 = 8 -> conflict-free
#define ASTAGE (BM * AST)   // 2560 floats
#define BSTAGE (BK * BST)   // 2176 floats
#define NSTG 4
#define STG_FLOATS (ASTAGE + BSTAGE)                 // 4736
#define SMEM_BYTES (NSTG * STG_FLOATS * 4)           // 75776 B per CTA

// Scratch (allocation-free rule: __device__ globals)
__device__ float g_Q[(size_t)NTOK * DM];
__device__ float g_K[(size_t)NTOK * DM];
__device__ float g_V[(size_t)NTOK * DM];
__device__ float g_X[(size_t)NTOK * DM];      // tf32-rounded x
__device__ float g_W[3][(size_t)DM * DM];     // tf32-rounded Wq, Wk, Wv (original [k][n] layout)
__device__ float g_cos[4096 * 32];
__device__ float g_sin[4096 * 32];

__device__ __forceinline__ uint32_t to_tf32(float x) {
    uint32_t u;
    asm("cvt.rna.tf32.f32 %0, %1;" : "=r"(u) : "f"(x));
    return u;
}

__device__ __forceinline__ void cp16(uint32_t saddr, const float* g) {
    asm volatile("cp.async.cg.shared.global [%0], [%1], 16;\n" ::"r"(saddr), "l"(g));
}

// Round fp32 -> tf32 (rna), store as fp32 (tf32 values are exact fp32)
__global__ void cvt_tf32_kernel(const float4* __restrict__ src, float4* __restrict__ dst, int n4) {
    int i = blockIdx.x * blockDim.x + threadIdx.x;
    if (i >= n4) return;
    float4 v = src[i];
    float4 o;
    o.x = __uint_as_float(to_tf32(v.x));
    o.y = __uint_as_float(to_tf32(v.y));
    o.z = __uint_as_float(to_tf32(v.z));
    o.w = __uint_as_float(to_tf32(v.w));
    dst[i] = o;
}

// RoPE table: 32 fp64 exps total, fast sincos on exactly range-reduced angle.
__global__ void rope_table_kernel() {
    int k = blockIdx.x;  // 0..31
    double freq = exp((double)(-2 * k) * (log(10000.0) / 1024.0));
    const double TWO_PI = 6.283185307179586476925287;
    for (int s = threadIdx.x; s < 4096; s += blockDim.x) {
        double ang = (double)s * freq;
        double n = floor(ang * (1.0 / TWO_PI) + 0.5);
        float r = (float)(ang - n * TWO_PI);
        float ss, cc;
        __sincosf(r, &ss, &cc);
        g_cos[s * 32 + k] = cc;
        g_sin[s * 32 + k] = ss;
    }
}

// C[M,N] = X[M,K] @ W[K,N] + bias (+ optional fused RoPE). X, W pre-rounded to tf32.
// 256 threads, block 128x128, warp tile 64x32, 4-stage cp.async pipeline.
__global__ __launch_bounds__(256, 2)
void gemm_kernel(const float* __restrict__ X, const float* __restrict__ W,
                 const float* __restrict__ bias, float* __restrict__ out,
                 int do_rope) {
    extern __shared__ float sm[];
    int tid = threadIdx.x;
    int lane = tid & 31;
    int warp = tid >> 5;
    int g = lane >> 2;
    int t = lane & 3;
    int wm = (warp >> 2) * 64;   // 2(M) x 4(N) warp grid, warp tile 64x32
    int wn = (warp & 3) * 32;
    int bm = blockIdx.y * BM;
    int bn = blockIdx.x * BN;

    float acc[4][4][4];
#pragma unroll
    for (int i = 0; i < 4; i++)
#pragma unroll
        for (int j = 0; j < 4; j++)
#pragma unroll
            for (int c = 0; c < 4; c++) acc[i][j][c] = 0.f;

    uint32_t sbase = (uint32_t)__cvta_generic_to_shared(sm);

    // Per stage: A 128x16 floats = 512 16B-chunks (2/thread), B 16x128 = 512 chunks (2/thread)
    auto issue_stage = [&](int kt) {
        int s = kt & (NSTG - 1);
        int k0 = kt * BK;
        uint32_t ab = sbase + (uint32_t)(s * STG_FLOATS) * 4u;
        uint32_t bb = ab + (uint32_t)ASTAGE * 4u;
#pragma unroll
        for (int u = 0; u < 2; u++) {
            int c = tid + u * 256;
            int r = c >> 2, q = c & 3;
            cp16(ab + (uint32_t)(r * AST + q * 4) * 4u,
                 X + (size_t)(bm + r) * DM + k0 + q * 4);
        }
#pragma unroll
        for (int u = 0; u < 2; u++) {
            int c = tid + u * 256;
            int r = c >> 5, q = c & 31;
            cp16(bb + (uint32_t)(r * BST + q * 4) * 4u,
                 W + (size_t)(k0 + r) * DM + bn + q * 4);
        }
    };

    issue_stage(0);
    asm volatile("cp.async.commit_group;\n" ::);
    issue_stage(1);
    asm volatile("cp.async.commit_group;\n" ::);
    issue_stage(2);
    asm volatile("cp.async.commit_group;\n" ::);

    const int NKT = DM / BK;  // 64
    for (int kt = 0; kt < NKT; kt++) {
        asm volatile("cp.async.wait_group 2;\n" ::);
        __syncthreads();
        if (kt + 3 < NKT) issue_stage(kt + 3);
        asm volatile("cp.async.commit_group;\n" ::);

        int s = kt & (NSTG - 1);
        const float* As = sm + s * STG_FLOATS;
        const float* Bs = As + ASTAGE;

#pragma unroll
        for (int ks = 0; ks < 2; ks++) {
            int kb = ks * 8;
            uint32_t a[4][4], b[4][2];
#pragma unroll
            for (int mi = 0; mi < 4; mi++) {
                int row = wm + mi * 16 + g;
                const float* ap = As + row * AST + kb + t;
                a[mi][0] = __float_as_uint(ap[0]);
                a[mi][1] = __float_as_uint(ap[8 * AST]);
                a[mi][2] = __float_as_uint(ap[4]);
                a[mi][3] = __float_as_uint(ap[8 * AST + 4]);
            }
#pragma unroll
            for (int ni = 0; ni < 4; ni++) {
                int col = wn + ni * 8 + g;
                const float* bp = Bs + (kb + t) * BST + col;
                b[ni][0] = __float_as_uint(bp[0]);
                b[ni][1] = __float_as_uint(bp[4 * BST]);
            }
#pragma unroll
            for (int mi = 0; mi < 4; mi++)
#pragma unroll
                for (int ni = 0; ni < 4; ni++)
                    asm volatile(
                        "mma.sync.aligned.m16n8k8.row.col.f32.tf32.tf32.f32 "
                        "{%0,%1,%2,%3}, {%4,%5,%6,%7}, {%8,%9}, {%0,%1,%2,%3};"
                        : "+f"(acc[mi][ni][0]), "+f"(acc[mi][ni][1]),
                          "+f"(acc[mi][ni][2]), "+f"(acc[mi][ni][3])
                        : "r"(a[mi][0]), "r"(a[mi][1]), "r"(a[mi][2]), "r"(a[mi][3]),
                          "r"(b[ni][0]), "r"(b[ni][1]));
        }
        __syncthreads();
    }

    // Epilogue: bias add (+ fused RoPE rotation on (even,odd) column pairs)
#pragma unroll
    for (int mi = 0; mi < 4; mi++) {
        int r0 = bm + wm + mi * 16 + g;
#pragma unroll
        for (int ni = 0; ni < 4; ni++) {
            int col = bn + wn + ni * 8 + 2 * t;  // even column
            float b0 = bias[col], b1 = bias[col + 1];
#pragma unroll
            for (int h = 0; h < 2; h++) {
                int r = r0 + h * 8;
                float xe = acc[mi][ni][2 * h] + b0;
                float xo = acc[mi][ni][2 * h + 1] + b1;
                float2 v;
                if (do_rope) {
                    int kp = (col & 63) >> 1;
                    int ss = r & SEQ_MASK;
                    float c = g_cos[ss * 32 + kp];
                    float sn = g_sin[ss * 32 + kp];
                    v.x = xe * c - xo * sn;
                    v.y = xe * sn + xo * c;
                } else {
                    v.x = xe;
                    v.y = xo;
                }
                *(float2*)(out + (size_t)r * DM + col) = v;
            }
        }
    }
}

// Per-token attention over heads (Q/K already roped by GEMM epilogue).
__global__ __launch_bounds__(128)
void attn_kernel(float* __restrict__ out) {
    __shared__ __align__(16) float q[16][68];
    __shared__ __align__(16) float kk[16][68];
    __shared__ __align__(16) float v[16][68];
    __shared__ float sc[16][16];

    int tok = blockIdx.x;
    int tid = threadIdx.x;
    size_t base = (size_t)tok * DM;
    const float4* Q4 = (const float4*)(g_Q + base);
    const float4* K4 = (const float4*)(g_K + base);
    const float4* V4 = (const float4*)(g_V + base);

#pragma unroll
    for (int u = 0; u < 2; u++) {
        int c = tid + u * 128;
        int r = c >> 4, cc = c & 15;
        *(float4*)&q[r][cc * 4] = Q4[c];
        *(float4*)&kk[r][cc * 4] = K4[c];
        *(float4*)&v[r][cc * 4] = V4[c];
    }
    __syncthreads();

#pragma unroll
    for (int u = 0; u < 2; u++) {
        int p = tid + u * 128;
        int i = p >> 4, j = p & 15;
        const float4* qi = (const float4*)&q[i][0];
        const float4* kj = (const float4*)&kk[j][0];
        float a = 0.f;
#pragma unroll
        for (int d = 0; d < 16; d++) {
            float4 a4 = qi[d], b4 = kj[d];
            a += a4.x * b4.x + a4.y * b4.y + a4.z * b4.z + a4.w * b4.w;
        }
        sc[i][j] = a * 0.125f;  // 1/sqrt(64)
    }
    __syncthreads();

    if (tid < 16) {
        float m = sc[tid][0];
#pragma unroll
        for (int j = 1; j < 16; j++) m = fmaxf(m, sc[tid][j]);
        float sum = 0.f;
#pragma unroll
        for (int j = 0; j < 16; j++) {
            float e = __expf(sc[tid][j] - m);
            sc[tid][j] = e;
            sum += e;
        }
        float inv = 1.f / sum;
#pragma unroll
        for (int j = 0; j < 16; j++) sc[tid][j] *= inv;
    }
    __syncthreads();

    int i = tid >> 3, d0 = (tid & 7) * 8;
    float4 o0 = {0, 0, 0, 0}, o1 = {0, 0, 0, 0};
#pragma unroll
    for (int j = 0; j < 16; j++) {
        float a = sc[i][j];
        float4 v0 = *(const float4*)&v[j][d0];
        float4 v1 = *(const float4*)&v[j][d0 + 4];
        o0.x += a * v0.x; o0.y += a * v0.y; o0.z += a * v0.z; o0.w += a * v0.w;
        o1.x += a * v1.x; o1.y += a * v1.y; o1.z += a * v1.z; o1.w += a * v1.w;
    }
    *(float4*)(out + base + i * 64 + d0) = o0;
    *(float4*)(out + base + i * 64 + d0 + 4) = o1;
}

extern "C" void kernel_launch(void* const* d_in, const int* in_sizes, int n_in,
                              void* d_out, int out_size) {
    const float* x  = (const float*)d_in[0];
    const float* Wq = (const float*)d_in[1];
    const float* bq = (const float*)d_in[2];
    const float* Wk = (const float*)d_in[3];
    const float* bk = (const float*)d_in[4];
    const float* Wv = (const float*)d_in[5];
    const float* bv = (const float*)d_in[6];
    float* out = (float*)d_out;

    float *qp, *kp, *vp, *xp, *wp;
    cudaGetSymbolAddress((void**)&qp, g_Q);
    cudaGetSymbolAddress((void**)&kp, g_K);
    cudaGetSymbolAddress((void**)&vp, g_V);
    cudaGetSymbolAddress((void**)&xp, g_X);
    cudaGetSymbolAddress((void**)&wp, g_W);

    cudaFuncSetAttribute(gemm_kernel, cudaFuncAttributeMaxDynamicSharedMemorySize,
                         SMEM_BYTES);

    rope_table_kernel<<<32, 128>>>();

    int n4x = NTOK * DM / 4;
    cvt_tf32_kernel<<<n4x / 256, 256>>>((const float4*)x, (float4*)xp, n4x);
    int n4w = DM * DM / 4;
    cvt_tf32_kernel<<<n4w / 256, 256>>>((const float4*)Wq, (float4*)(wp + 0 * (size_t)DM * DM), n4w);
    cvt_tf32_kernel<<<n4w / 256, 256>>>((const float4*)Wk, (float4*)(wp + 1 * (size_t)DM * DM), n4w);
    cvt_tf32_kernel<<<n4w / 256, 256>>>((const float4*)Wv, (float4*)(wp + 2 * (size_t)DM * DM), n4w);

    dim3 grid(DM / BN, NTOK / BM);  // (8, 128)
    gemm_kernel<<<grid, 256, SMEM_BYTES>>>(xp, wp + 0 * (size_t)DM * DM, bq, qp, 1);
    gemm_kernel<<<grid, 256, SMEM_BYTES>>>(xp, wp + 1 * (size_t)DM * DM, bk, kp, 1);
    gemm_kernel<<<grid, 256, SMEM_BYTES>>>(xp, wp + 2 * (size_t)DM * DM, bv, vp, 0);

    attn_kernel<<<NTOK, 128>>>(out);
}

// round 12
// speedup vs baseline: 1.9050x; 1.6396x over previous
#include <cuda_runtime.h>
#include <cuda_fp16.h>
#include <cstdint>
#include <math.h>

#define NTOK 16384
#define SEQ_MASK 4095
#define DM 1024
#define BM 128
#define BN 128
#define BKH 64      // K halves per stage (128B/row)
#define ASTH 72     // smem row stride in halves (144B): conflict-free for frag LDS
#define A_H (BM * ASTH)           // 9216 halves
#define B_H (BN * ASTH)           // 9216 halves
#define STG_H (A_H + B_H)         // 18432 halves = 36864 B
#define NSTG 3
#define SMEM_BYTES (NSTG * STG_H * 2)   // 110592 B

// Scratch (allocation-free rule: __device__ globals)
__device__ float g_Q[(size_t)NTOK * DM];
__device__ float g_K[(size_t)NTOK * DM];
__device__ float g_V[(size_t)NTOK * DM];
__device__ __half g_Xh[(size_t)NTOK * DM];       // half(x), [M][K]
__device__ __half g_Wh[3][(size_t)DM * DM];      // half(W)^T, [N][K] per matrix
__device__ float g_cos[4096 * 32];
__device__ float g_sin[4096 * 32];

__device__ __forceinline__ void cp16(uint32_t saddr, const void* g) {
    asm volatile("cp.async.cg.shared.global [%0], [%1], 16;\n" ::"r"(saddr), "l"(g));
}

// ---- x -> half, same layout ----
__global__ void cvt_x_half(const float4* __restrict__ src, __half2* __restrict__ dst, int n4) {
    int i = blockIdx.x * blockDim.x + threadIdx.x;
    if (i >= n4) return;
    float4 v = src[i];
    dst[2 * i]     = __float22half2_rn(make_float2(v.x, v.y));
    dst[2 * i + 1] = __float22half2_rn(make_float2(v.z, v.w));
}

// ---- W[k][n] -> half W^T[n][k] ----
__global__ void cvt_w_half(const float* __restrict__ W, __half* __restrict__ Wt) {
    __shared__ float t[32][33];
    int bn = blockIdx.x * 32, bk = blockIdx.y * 32;
    int tx = threadIdx.x, ty = threadIdx.y;
#pragma unroll
    for (int i = ty; i < 32; i += 8)
        t[i][tx] = W[(size_t)(bk + i) * DM + bn + tx];
    __syncthreads();
#pragma unroll
    for (int i = ty; i < 32; i += 8)
        Wt[(size_t)(bn + i) * DM + bk + tx] = __float2half_rn(t[tx][i]);
}

// RoPE table: 32 fp64 exps total, fast sincos on exactly range-reduced angle.
__global__ void rope_table_kernel() {
    int k = blockIdx.x;  // 0..31
    double freq = exp((double)(-2 * k) * (log(10000.0) / 1024.0));
    const double TWO_PI = 6.283185307179586476925287;
    for (int s = threadIdx.x; s < 4096; s += blockDim.x) {
        double ang = (double)s * freq;
        double n = floor(ang * (1.0 / TWO_PI) + 0.5);
        float r = (float)(ang - n * TWO_PI);
        float ss, cc;
        __sincosf(r, &ss, &cc);
        g_cos[s * 32 + k] = cc;
        g_sin[s * 32 + k] = ss;
    }
}

// out[M,N] = Xh[M,K] @ Wt[N,K]^T + bias (+RoPE for z<2). fp16 inputs, fp32 accum.
// blockIdx.z selects {Q,K,V}. 256 threads, block 128x128, warp 64x32, 3-stage cp.async.
__global__ __launch_bounds__(256, 2)
void gemm_kernel(const __half* __restrict__ Xh,
                 const float* __restrict__ bq, const float* __restrict__ bk,
                 const float* __restrict__ bv) {
    extern __shared__ __half smh[];
    int z = blockIdx.z;
    const __half* W = g_Wh[z];
    const float* bias = (z == 0) ? bq : (z == 1) ? bk : bv;
    float* out = (z == 0) ? g_Q : (z == 1) ? g_K : g_V;
    int do_rope = (z < 2);

    int tid = threadIdx.x;
    int lane = tid & 31;
    int warp = tid >> 5;
    int g = lane >> 2;
    int t = lane & 3;
    int wm = (warp >> 2) * 64;   // 2(M) x 4(N) warp grid, warp tile 64x32
    int wn = (warp & 3) * 32;
    int bm = blockIdx.y * BM;
    int bn = blockIdx.x * BN;

    float acc[4][4][4];
#pragma unroll
    for (int i = 0; i < 4; i++)
#pragma unroll
        for (int j = 0; j < 4; j++)
#pragma unroll
            for (int c = 0; c < 4; c++) acc[i][j][c] = 0.f;

    uint32_t sbase = (uint32_t)__cvta_generic_to_shared(smh);

    // Per stage: A = 128 rows x 128B = 1024 16B-chunks (4/thread); B same.
    auto issue_stage = [&](int kt) {
        int s = kt % NSTG;
        int k0 = kt * BKH;
        uint32_t ab = sbase + (uint32_t)(s * STG_H) * 2u;
        uint32_t bb = ab + (uint32_t)A_H * 2u;
#pragma unroll
        for (int u = 0; u < 4; u++) {
            int c = tid + u * 256;
            int r = c >> 3, q = c & 7;
            cp16(ab + (uint32_t)(r * ASTH + q * 8) * 2u,
                 Xh + (size_t)(bm + r) * DM + k0 + q * 8);
        }
#pragma unroll
        for (int u = 0; u < 4; u++) {
            int c = tid + u * 256;
            int r = c >> 3, q = c & 7;
            cp16(bb + (uint32_t)(r * ASTH + q * 8) * 2u,
                 W + (size_t)(bn + r) * DM + k0 + q * 8);
        }
    };

    issue_stage(0);
    asm volatile("cp.async.commit_group;\n" ::);
    issue_stage(1);
    asm volatile("cp.async.commit_group;\n" ::);

    const int NKT = DM / BKH;  // 16
    for (int kt = 0; kt < NKT; kt++) {
        asm volatile("cp.async.wait_group 1;\n" ::);
        __syncthreads();
        if (kt + 2 < NKT) issue_stage(kt + 2);
        asm volatile("cp.async.commit_group;\n" ::);

        int s = kt % NSTG;
        const __half* As = smh + s * STG_H;
        const __half* Bs = As + A_H;

#pragma unroll
        for (int sub = 0; sub < 4; sub++) {
            int kb = sub * 16;
            uint32_t a[4][4], b[4][2];
#pragma unroll
            for (int mi = 0; mi < 4; mi++) {
                int row = wm + mi * 16 + g;
                const __half* ap = As + row * ASTH + kb + 2 * t;
                a[mi][0] = *(const uint32_t*)(ap);
                a[mi][1] = *(const uint32_t*)(ap + 8 * ASTH);
                a[mi][2] = *(const uint32_t*)(ap + 8);
                a[mi][3] = *(const uint32_t*)(ap + 8 * ASTH + 8);
            }
#pragma unroll
            for (int ni = 0; ni < 4; ni++) {
                int col = wn + ni * 8 + g;
                const __half* bp = Bs + col * ASTH + kb + 2 * t;
                b[ni][0] = *(const uint32_t*)(bp);
                b[ni][1] = *(const uint32_t*)(bp + 8);
            }
#pragma unroll
            for (int mi = 0; mi < 4; mi++)
#pragma unroll
                for (int ni = 0; ni < 4; ni++)
                    asm volatile(
                        "mma.sync.aligned.m16n8k16.row.col.f32.f16.f16.f32 "
                        "{%0,%1,%2,%3}, {%4,%5,%6,%7}, {%8,%9}, {%0,%1,%2,%3};"
                        : "+f"(acc[mi][ni][0]), "+f"(acc[mi][ni][1]),
                          "+f"(acc[mi][ni][2]), "+f"(acc[mi][ni][3])
                        : "r"(a[mi][0]), "r"(a[mi][1]), "r"(a[mi][2]), "r"(a[mi][3]),
                          "r"(b[ni][0]), "r"(b[ni][1]));
        }
        __syncthreads();
    }

    // Epilogue: bias add (+ fused RoPE rotation on (even,odd) column pairs)
#pragma unroll
    for (int mi = 0; mi < 4; mi++) {
        int r0 = bm + wm + mi * 16 + g;
#pragma unroll
        for (int ni = 0; ni < 4; ni++) {
            int col = bn + wn + ni * 8 + 2 * t;  // even column
            float b0 = bias[col], b1 = bias[col + 1];
#pragma unroll
            for (int h = 0; h < 2; h++) {
                int r = r0 + h * 8;
                float xe = acc[mi][ni][2 * h] + b0;
                float xo = acc[mi][ni][2 * h + 1] + b1;
                float2 v;
                if (do_rope) {
                    int kp = (col & 63) >> 1;
                    int ss = r & SEQ_MASK;
                    float c = g_cos[ss * 32 + kp];
                    float sn = g_sin[ss * 32 + kp];
                    v.x = xe * c - xo * sn;
                    v.y = xe * sn + xo * c;
                } else {
                    v.x = xe;
                    v.y = xo;
                }
                *(float2*)(out + (size_t)r * DM + col) = v;
            }
        }
    }
}

// Per-token attention over heads (Q/K already roped by GEMM epilogue).
__global__ __launch_bounds__(128)
void attn_kernel(float* __restrict__ out) {
    __shared__ __align__(16) float q[16][68];
    __shared__ __align__(16) float kk[16][68];
    __shared__ __align__(16) float v[16][68];
    __shared__ float sc[16][16];

    int tok = blockIdx.x;
    int tid = threadIdx.x;
    size_t base = (size_t)tok * DM;
    const float4* Q4 = (const float4*)(g_Q + base);
    const float4* K4 = (const float4*)(g_K + base);
    const float4* V4 = (const float4*)(g_V + base);

#pragma unroll
    for (int u = 0; u < 2; u++) {
        int c = tid + u * 128;
        int r = c >> 4, cc = c & 15;
        *(float4*)&q[r][cc * 4] = Q4[c];
        *(float4*)&kk[r][cc * 4] = K4[c];
        *(float4*)&v[r][cc * 4] = V4[c];
    }
    __syncthreads();

#pragma unroll
    for (int u = 0; u < 2; u++) {
        int p = tid + u * 128;
        int i = p >> 4, j = p & 15;
        const float4* qi = (const float4*)&q[i][0];
        const float4* kj = (const float4*)&kk[j][0];
        float a = 0.f;
#pragma unroll
        for (int d = 0; d < 16; d++) {
            float4 a4 = qi[d], b4 = kj[d];
            a += a4.x * b4.x + a4.y * b4.y + a4.z * b4.z + a4.w * b4.w;
        }
        sc[i][j] = a * 0.125f;  // 1/sqrt(64)
    }
    __syncthreads();

    if (tid < 16) {
        float m = sc[tid][0];
#pragma unroll
        for (int j = 1; j < 16; j++) m = fmaxf(m, sc[tid][j]);
        float sum = 0.f;
#pragma unroll
        for (int j = 0; j < 16; j++) {
            float e = __expf(sc[tid][j] - m);
            sc[tid][j] = e;
            sum += e;
        }
        float inv = 1.f / sum;
#pragma unroll
        for (int j = 0; j < 16; j++) sc[tid][j] *= inv;
    }
    __syncthreads();

    int i = tid >> 3, d0 = (tid & 7) * 8;
    float4 o0 = {0, 0, 0, 0}, o1 = {0, 0, 0, 0};
#pragma unroll
    for (int j = 0; j < 16; j++) {
        float a = sc[i][j];
        float4 v0 = *(const float4*)&v[j][d0];
        float4 v1 = *(const float4*)&v[j][d0 + 4];
        o0.x += a * v0.x; o0.y += a * v0.y; o0.z += a * v0.z; o0.w += a * v0.w;
        o1.x += a * v1.x; o1.y += a * v1.y; o1.z += a * v1.z; o1.w += a * v1.w;
    }
    *(float4*)(out + base + i * 64 + d0) = o0;
    *(float4*)(out + base + i * 64 + d0 + 4) = o1;
}

extern "C" void kernel_launch(void* const* d_in, const int* in_sizes, int n_in,
                              void* d_out, int out_size) {
    const float* x  = (const float*)d_in[0];
    const float* Wq = (const float*)d_in[1];
    const float* bq = (const float*)d_in[2];
    const float* Wk = (const float*)d_in[3];
    const float* bk = (const float*)d_in[4];
    const float* Wv = (const float*)d_in[5];
    const float* bv = (const float*)d_in[6];
    float* out = (float*)d_out;

    __half *xhp, *whp;
    cudaGetSymbolAddress((void**)&xhp, g_Xh);
    cudaGetSymbolAddress((void**)&whp, g_Wh);

    cudaFuncSetAttribute(gemm_kernel, cudaFuncAttributeMaxDynamicSharedMemorySize,
                         SMEM_BYTES);

    rope_table_kernel<<<32, 128>>>();

    int n4x = NTOK * DM / 4;
    cvt_x_half<<<n4x / 256, 256>>>((const float4*)x, (__half2*)xhp, n4x);
    dim3 tgrid(DM / 32, DM / 32), tblk(32, 8);
    cvt_w_half<<<tgrid, tblk>>>(Wq, whp + 0 * (size_t)DM * DM);
    cvt_w_half<<<tgrid, tblk>>>(Wk, whp + 1 * (size_t)DM * DM);
    cvt_w_half<<<tgrid, tblk>>>(Wv, whp + 2 * (size_t)DM * DM);

    dim3 grid(DM / BN, NTOK / BM, 3);  // (8, 128, 3)
    gemm_kernel<<<grid, 256, SMEM_BYTES>>>(xhp, bq, bk, bv);

    attn_kernel<<<NTOK, 128>>>(out);
}

// round 14
// speedup vs baseline: 2.0194x; 1.0600x over previous
#include <cuda_runtime.h>
#include <cuda_fp16.h>
#include <cstdint>
#include <math.h>

#define NTOK 16384
#define SEQ_MASK 4095
#define DM 1024
#define BM 128
#define BN 128
#define BKH 64      // K halves per stage (128B/row)
#define ASTH 72     // smem row stride in halves (144B): banks shift 4/row -> LDSM conflict-free
#define A_H (BM * ASTH)           // 9216 halves
#define B_H (BN * ASTH)           // 9216 halves
#define STG_H (A_H + B_H)         // 18432 halves = 36864 B
#define NSTG 3
#define SMEM_BYTES (NSTG * STG_H * 2)   // 110592 B

// Scratch (allocation-free rule: __device__ globals)
__device__ __half g_Q[(size_t)NTOK * DM];
__device__ __half g_K[(size_t)NTOK * DM];
__device__ __half g_V[(size_t)NTOK * DM];
__device__ __half g_Xh[(size_t)NTOK * DM];       // half(x), [M][K]
__device__ __half g_Wh[3][(size_t)DM * DM];      // half(W)^T, [N][K] per matrix
__device__ float g_cos[4096 * 32];
__device__ float g_sin[4096 * 32];

__device__ __forceinline__ void cp16(uint32_t saddr, const void* g) {
    asm volatile("cp.async.cg.shared.global [%0], [%1], 16;\n" ::"r"(saddr), "l"(g));
}

__device__ __forceinline__ void ldsm4(uint32_t& r0, uint32_t& r1, uint32_t& r2, uint32_t& r3,
                                      uint32_t saddr) {
    asm volatile("ldmatrix.sync.aligned.m8n8.x4.shared.b16 {%0,%1,%2,%3}, [%4];"
                 : "=r"(r0), "=r"(r1), "=r"(r2), "=r"(r3) : "r"(saddr));
}

// ---- x -> half, same layout ----
__global__ void cvt_x_half(const float4* __restrict__ src, __half2* __restrict__ dst, int n4) {
    int i = blockIdx.x * blockDim.x + threadIdx.x;
    if (i >= n4) return;
    float4 v = src[i];
    dst[2 * i]     = __float22half2_rn(make_float2(v.x, v.y));
    dst[2 * i + 1] = __float22half2_rn(make_float2(v.z, v.w));
}

// ---- W[k][n] -> half W^T[n][k] ----
__global__ void cvt_w_half(const float* __restrict__ W, __half* __restrict__ Wt) {
    __shared__ float t[32][33];
    int bn = blockIdx.x * 32, bk = blockIdx.y * 32;
    int tx = threadIdx.x, ty = threadIdx.y;
#pragma unroll
    for (int i = ty; i < 32; i += 8)
        t[i][tx] = W[(size_t)(bk + i) * DM + bn + tx];
    __syncthreads();
#pragma unroll
    for (int i = ty; i < 32; i += 8)
        Wt[(size_t)(bn + i) * DM + bk + tx] = __float2half_rn(t[tx][i]);
}

// RoPE table: 32 fp64 exps total, fast sincos on exactly range-reduced angle.
__global__ void rope_table_kernel() {
    int k = blockIdx.x;  // 0..31
    double freq = exp((double)(-2 * k) * (log(10000.0) / 1024.0));
    const double TWO_PI = 6.283185307179586476925287;
    for (int s = threadIdx.x; s < 4096; s += blockDim.x) {
        double ang = (double)s * freq;
        double n = floor(ang * (1.0 / TWO_PI) + 0.5);
        float r = (float)(ang - n * TWO_PI);
        float ss, cc;
        __sincosf(r, &ss, &cc);
        g_cos[s * 32 + k] = cc;
        g_sin[s * 32 + k] = ss;
    }
}

// out[M,N] = Xh[M,K] @ Wt[N,K]^T + bias (+RoPE for z<2). fp16 in, fp32 accum, half out.
// blockIdx.z selects {Q,K,V}. 256 threads, block 128x128, warp 64x32, 3-stage cp.async.
__global__ __launch_bounds__(256, 2)
void gemm_kernel(const __half* __restrict__ Xh,
                 const float* __restrict__ bq, const float* __restrict__ bk,
                 const float* __restrict__ bv) {
    extern __shared__ __half smh[];
    int z = blockIdx.z;
    const __half* W = g_Wh[z];
    const float* bias = (z == 0) ? bq : (z == 1) ? bk : bv;
    __half* out = (z == 0) ? g_Q : (z == 1) ? g_K : g_V;
    int do_rope = (z < 2);

    int tid = threadIdx.x;
    int lane = tid & 31;
    int warp = tid >> 5;
    int g = lane >> 2;
    int t = lane & 3;
    int wm = (warp >> 2) * 64;   // 2(M) x 4(N) warp grid, warp tile 64x32
    int wn = (warp & 3) * 32;
    int bm = blockIdx.y * BM;
    int bn = blockIdx.x * BN;

    int qd = lane >> 3, lr = lane & 7;
    // ldmatrix per-lane offsets (halves):
    int a_row = wm + ((qd & 1) << 3) + lr;        // + mi*16
    int a_col = (qd >> 1) << 3;                   // + kb
    int b_row = wn + ((qd >> 1) << 3) + lr;       // + ni0*8
    int b_col = (qd & 1) << 3;                    // + kb

    float acc[4][4][4];
#pragma unroll
    for (int i = 0; i < 4; i++)
#pragma unroll
        for (int j = 0; j < 4; j++)
#pragma unroll
            for (int c = 0; c < 4; c++) acc[i][j][c] = 0.f;

    uint32_t sbase = (uint32_t)__cvta_generic_to_shared(smh);

    auto issue_stage = [&](int kt) {
        int s = kt % NSTG;
        int k0 = kt * BKH;
        uint32_t ab = sbase + (uint32_t)(s * STG_H) * 2u;
        uint32_t bb = ab + (uint32_t)A_H * 2u;
#pragma unroll
        for (int u = 0; u < 4; u++) {
            int c = tid + u * 256;
            int r = c >> 3, q = c & 7;
            cp16(ab + (uint32_t)(r * ASTH + q * 8) * 2u,
                 Xh + (size_t)(bm + r) * DM + k0 + q * 8);
        }
#pragma unroll
        for (int u = 0; u < 4; u++) {
            int c = tid + u * 256;
            int r = c >> 3, q = c & 7;
            cp16(bb + (uint32_t)(r * ASTH + q * 8) * 2u,
                 W + (size_t)(bn + r) * DM + k0 + q * 8);
        }
    };

    issue_stage(0);
    asm volatile("cp.async.commit_group;\n" ::);
    issue_stage(1);
    asm volatile("cp.async.commit_group;\n" ::);

    const int NKT = DM / BKH;  // 16
    for (int kt = 0; kt < NKT; kt++) {
        asm volatile("cp.async.wait_group 1;\n" ::);
        __syncthreads();
        if (kt + 2 < NKT) issue_stage(kt + 2);
        asm volatile("cp.async.commit_group;\n" ::);

        int s = kt % NSTG;
        uint32_t As = sbase + (uint32_t)(s * STG_H) * 2u;
        uint32_t Bs = As + (uint32_t)A_H * 2u;

#pragma unroll
        for (int sub = 0; sub < 4; sub++) {
            int kb = sub * 16;
            uint32_t a[4][4], b[4][2];
#pragma unroll
            for (int mi = 0; mi < 4; mi++)
                ldsm4(a[mi][0], a[mi][1], a[mi][2], a[mi][3],
                      As + (uint32_t)((a_row + mi * 16) * ASTH + kb + a_col) * 2u);
#pragma unroll
            for (int np = 0; np < 2; np++)
                ldsm4(b[2 * np][0], b[2 * np][1], b[2 * np + 1][0], b[2 * np + 1][1],
                      Bs + (uint32_t)((b_row + np * 16) * ASTH + kb + b_col) * 2u);
#pragma unroll
            for (int mi = 0; mi < 4; mi++)
#pragma unroll
                for (int ni = 0; ni < 4; ni++)
                    asm volatile(
                        "mma.sync.aligned.m16n8k16.row.col.f32.f16.f16.f32 "
                        "{%0,%1,%2,%3}, {%4,%5,%6,%7}, {%8,%9}, {%0,%1,%2,%3};"
                        : "+f"(acc[mi][ni][0]), "+f"(acc[mi][ni][1]),
                          "+f"(acc[mi][ni][2]), "+f"(acc[mi][ni][3])
                        : "r"(a[mi][0]), "r"(a[mi][1]), "r"(a[mi][2]), "r"(a[mi][3]),
                          "r"(b[ni][0]), "r"(b[ni][1]));
        }
    }

    // Epilogue: bias add (+ fused RoPE rotation), write half2
#pragma unroll
    for (int mi = 0; mi < 4; mi++) {
        int r0 = bm + wm + mi * 16 + g;
#pragma unroll
        for (int ni = 0; ni < 4; ni++) {
            int col = bn + wn + ni * 8 + 2 * t;  // even column
            float b0 = bias[col], b1 = bias[col + 1];
#pragma unroll
            for (int h = 0; h < 2; h++) {
                int r = r0 + h * 8;
                float xe = acc[mi][ni][2 * h] + b0;
                float xo = acc[mi][ni][2 * h + 1] + b1;
                float2 v;
                if (do_rope) {
                    int kp = (col & 63) >> 1;
                    int ss = r & SEQ_MASK;
                    float c = g_cos[ss * 32 + kp];
                    float sn = g_sin[ss * 32 + kp];
                    v.x = xe * c - xo * sn;
                    v.y = xe * sn + xo * c;
                } else {
                    v.x = xe;
                    v.y = xo;
                }
                *(__half2*)(out + (size_t)r * DM + col) = __float22half2_rn(v);
            }
        }
    }
}

// Per-token attention over heads (Q/K already roped by GEMM epilogue). Half inputs.
__global__ __launch_bounds__(128)
void attn_kernel(float* __restrict__ out) {
    __shared__ __align__(16) float q[16][68];
    __shared__ __align__(16) float kk[16][68];
    __shared__ __align__(16) float v[16][68];
    __shared__ float sc[16][16];

    int tok = blockIdx.x;
    int tid = threadIdx.x;
    size_t base = (size_t)tok * DM;
    const uint4* Q4 = (const uint4*)(g_Q + base);
    const uint4* K4 = (const uint4*)(g_K + base);
    const uint4* V4 = (const uint4*)(g_V + base);

    // 1024 halves per matrix = 128 uint4 chunks; 1 chunk/thread/matrix
    {
        int c = tid;
        int r = c >> 3, cc = c & 7;  // row, 8-half chunk
        uint4 uq = Q4[c], uk = K4[c], uv = V4[c];
#pragma unroll
        for (int m = 0; m < 3; m++) {
            uint4 u = (m == 0) ? uq : (m == 1) ? uk : uv;
            float* dst = (m == 0) ? &q[r][cc * 8] : (m == 1) ? &kk[r][cc * 8] : &v[r][cc * 8];
            float2 f0 = __half22float2(*(__half2*)&u.x);
            float2 f1 = __half22float2(*(__half2*)&u.y);
            float2 f2 = __half22float2(*(__half2*)&u.z);
            float2 f3 = __half22float2(*(__half2*)&u.w);
            dst[0] = f0.x; dst[1] = f0.y; dst[2] = f1.x; dst[3] = f1.y;
            dst[4] = f2.x; dst[5] = f2.y; dst[6] = f3.x; dst[7] = f3.y;
        }
    }
    __syncthreads();

#pragma unroll
    for (int u = 0; u < 2; u++) {
        int p = tid + u * 128;
        int i = p >> 4, j = p & 15;
        const float4* qi = (const float4*)&q[i][0];
        const float4* kj = (const float4*)&kk[j][0];
        float a = 0.f;
#pragma unroll
        for (int d = 0; d < 16; d++) {
            float4 a4 = qi[d], b4 = kj[d];
            a += a4.x * b4.x + a4.y * b4.y + a4.z * b4.z + a4.w * b4.w;
        }
        sc[i][j] = a * 0.125f;  // 1/sqrt(64)
    }
    __syncthreads();

    if (tid < 16) {
        float m = sc[tid][0];
#pragma unroll
        for (int j = 1; j < 16; j++) m = fmaxf(m, sc[tid][j]);
        float sum = 0.f;
#pragma unroll
        for (int j = 0; j < 16; j++) {
            float e = __expf(sc[tid][j] - m);
            sc[tid][j] = e;
            sum += e;
        }
        float inv = 1.f / sum;
#pragma unroll
        for (int j = 0; j < 16; j++) sc[tid][j] *= inv;
    }
    __syncthreads();

    int i = tid >> 3, d0 = (tid & 7) * 8;
    float4 o0 = {0, 0, 0, 0}, o1 = {0, 0, 0, 0};
#pragma unroll
    for (int j = 0; j < 16; j++) {
        float a = sc[i][j];
        float4 v0 = *(const float4*)&v[j][d0];
        float4 v1 = *(const float4*)&v[j][d0 + 4];
        o0.x += a * v0.x; o0.y += a * v0.y; o0.z += a * v0.z; o0.w += a * v0.w;
        o1.x += a * v1.x; o1.y += a * v1.y; o1.z += a * v1.z; o1.w += a * v1.w;
    }
    *(float4*)(out + base + i * 64 + d0) = o0;
    *(float4*)(out + base + i * 64 + d0 + 4) = o1;
}

extern "C" void kernel_launch(void* const* d_in, const int* in_sizes, int n_in,
                              void* d_out, int out_size) {
    const float* x  = (const float*)d_in[0];
    const float* Wq = (const float*)d_in[1];
    const float* bq = (const float*)d_in[2];
    const float* Wk = (const float*)d_in[3];
    const float* bk = (const float*)d_in[4];
    const float* Wv = (const float*)d_in[5];
    const float* bv = (const float*)d_in[6];
    float* out = (float*)d_out;

    __half *xhp, *whp;
    cudaGetSymbolAddress((void**)&xhp, g_Xh);
    cudaGetSymbolAddress((void**)&whp, g_Wh);

    cudaFuncSetAttribute(gemm_kernel, cudaFuncAttributeMaxDynamicSharedMemorySize,
                         SMEM_BYTES);

    rope_table_kernel<<<32, 128>>>();

    int n4x = NTOK * DM / 4;
    cvt_x_half<<<n4x / 256, 256>>>((const float4*)x, (__half2*)xhp, n4x);
    dim3 tgrid(DM / 32, DM / 32), tblk(32, 8);
    cvt_w_half<<<tgrid, tblk>>>(Wq, whp + 0 * (size_t)DM * DM);
    cvt_w_half<<<tgrid, tblk>>>(Wk, whp + 1 * (size_t)DM * DM);
    cvt_w_half<<<tgrid, tblk>>>(Wv, whp + 2 * (size_t)DM * DM);

    dim3 grid(DM / BN, NTOK / BM, 3);  // (8, 128, 3)
    gemm_kernel<<<grid, 256, SMEM_BYTES>>>(xhp, bq, bk, bv);

    attn_kernel<<<NTOK, 128>>>(out);
}